// round 17
// baseline (speedup 1.0000x reference)
#include <cuda_runtime.h>
#include <cuda_bf16.h>
#include <cuda_fp16.h>
#include <cstdint>
#include <math.h>

#define N_NODES 50000
#define E_MAX   800000
#define DIN     128
#define DH      256
#define DOUT    64
#define LAYERS  4

#define SCAN_NB  ((N_NODES + 1023) / 1024)   // 49

// ---------------- device scratch (allocation-free) ----------------
__device__ int   g_cnt[N_NODES];
__device__ int   g_partial[64];
__device__ int   g_rowptr[N_NODES + 1];
__device__ int   g_cursor[N_NODES];
__device__ int2  g_csr[E_MAX];                    // {src, norm-as-int}
__device__ __half g_x [(size_t)N_NODES * DIN];    // fp16 input features
__device__ __half g_h [(size_t)N_NODES * DH];     // fp16 activations
__device__ __half g_ht[(size_t)N_NODES * DH];     // fp16 pre-activation (gather path)
// transposed fp16 weights [N][K] (K-major rows)
__device__ __half g_wembh[DH * DIN], g_wembl[DH * DIN];
__device__ __half g_wconvh[LAYERS * DH * DH];     // conv: single-term fp16
__device__ __half g_wouth[DOUT * DH], g_woutl[DOUT * DH];

// ---------------- CSR build ----------------
__global__ void k_zero(int* cnt, int n) {
    int i = blockIdx.x * blockDim.x + threadIdx.x;
    if (i < n) cnt[i] = 0;
}
__global__ void k_count(const int* __restrict__ dst, int* cnt, int E) {
    int e = blockIdx.x * blockDim.x + threadIdx.x;
    if (e < E) atomicAdd(&cnt[dst[e]], 1);
}
__global__ void k_scan1(const int* __restrict__ cnt, int* partial, int n) {
    __shared__ int sd[256];
    int base = blockIdx.x * 1024;
    int t = threadIdx.x;
    int s = 0;
    #pragma unroll
    for (int i = 0; i < 4; i++) {
        int idx = base + t + i * 256;
        if (idx < n) s += cnt[idx];
    }
    sd[t] = s;
    __syncthreads();
    #pragma unroll
    for (int off = 128; off > 0; off >>= 1) {
        if (t < off) sd[t] += sd[t + off];
        __syncthreads();
    }
    if (t == 0) partial[blockIdx.x] = sd[0];
}
__global__ void k_scan2(int* partial, int* rowptr, int nb, int n) {
    __shared__ int sh[64];
    int t = threadIdx.x;
    int v = (t < nb) ? partial[t] : 0;
    sh[t] = v;
    __syncthreads();
    #pragma unroll
    for (int off = 1; off < 64; off <<= 1) {
        int x = (t >= off) ? sh[t - off] : 0;
        __syncthreads();
        sh[t] += x;
        __syncthreads();
    }
    if (t < nb) partial[t] = sh[t] - v;      // exclusive
    if (t == 63) rowptr[n] = sh[63];
}
__global__ void k_scan3(const int* __restrict__ cnt, const int* __restrict__ partial,
                        int* rowptr, int* cursor, int n) {
    __shared__ int sh[256];
    int base = blockIdx.x * 1024;
    int t = threadIdx.x;
    int i0 = base + t * 4;
    int c0 = (i0     < n) ? cnt[i0    ] : 0;
    int c1 = (i0 + 1 < n) ? cnt[i0 + 1] : 0;
    int c2 = (i0 + 2 < n) ? cnt[i0 + 2] : 0;
    int c3 = (i0 + 3 < n) ? cnt[i0 + 3] : 0;
    int tot = c0 + c1 + c2 + c3;
    sh[t] = tot;
    __syncthreads();
    #pragma unroll
    for (int off = 1; off < 256; off <<= 1) {
        int x = (t >= off) ? sh[t - off] : 0;
        __syncthreads();
        sh[t] += x;
        __syncthreads();
    }
    int run = sh[t] - tot + partial[blockIdx.x];
    if (i0     < n) { rowptr[i0    ] = run; cursor[i0    ] = run; run += c0; }
    if (i0 + 1 < n) { rowptr[i0 + 1] = run; cursor[i0 + 1] = run; run += c1; }
    if (i0 + 2 < n) { rowptr[i0 + 2] = run; cursor[i0 + 2] = run; run += c2; }
    if (i0 + 3 < n) { rowptr[i0 + 3] = run; cursor[i0 + 3] = run; }
}
// fill: computes edge weight from cnt directly (dinv = rsqrt(cnt+1))
__global__ void k_fill(const int* __restrict__ src, const int* __restrict__ dst,
                       const int* __restrict__ cnt, int* cursor,
                       int2* __restrict__ csr, int E) {
    int e = blockIdx.x * blockDim.x + threadIdx.x;
    if (e >= E) return;
    int s = src[e], d = dst[e];
    int pos = atomicAdd(&cursor[d], 1);
    float w = rsqrtf((float)cnt[s] + 1.0f) * rsqrtf((float)cnt[d] + 1.0f);
    csr[pos] = make_int2(s, __float_as_int(w));
}

// ---------------- conversions ----------------
__device__ __forceinline__ void split_fp16(float v, __half& hi, __half& lo) {
    hi = __float2half_rn(v);
    lo = __float2half_rn(v - __half2float(hi));
}
__global__ void k_conv_x(const float* __restrict__ x, __half* __restrict__ out, int total) {
    int i = blockIdx.x * blockDim.x + threadIdx.x;
    if (i >= total) return;
    out[i] = __float2half_rn(x[i]);
}
// W [K][N] fp32 -> out [N][K] fp16 hi/lo (emb / out weights)
__global__ void k_conv_w(const float* __restrict__ W,
                         __half* __restrict__ hi, __half* __restrict__ lo,
                         int K, int N) {
    int i = blockIdx.x * blockDim.x + threadIdx.x;
    if (i >= K * N) return;
    int k = i / N, n = i % N;
    __half h, l;
    split_fp16(W[i], h, l);
    hi[(size_t)n * K + k] = h;
    lo[(size_t)n * K + k] = l;
}
// all conv layers, single term fp16
__global__ void k_conv_wall(const float* __restrict__ W, __half* __restrict__ hi) {
    int i = blockIdx.x * blockDim.x + threadIdx.x;
    if (i >= LAYERS * DH * DH) return;
    int l = i / (DH * DH);
    int r = i % (DH * DH);
    int k = r / DH, n = r % DH;
    hi[(size_t)l * DH * DH + (size_t)n * DH + k] = __float2half_rn(W[i]);
}

// ---------------- mma.sync fp16 GEMM, cp.async 2-stage ----------------
__device__ __forceinline__ void mma16816(float* c, const uint32_t* a, const uint32_t* b) {
    asm volatile(
        "mma.sync.aligned.m16n8k16.row.col.f32.f16.f16.f32 "
        "{%0,%1,%2,%3}, {%4,%5,%6,%7}, {%8,%9}, {%0,%1,%2,%3};"
        : "+f"(c[0]), "+f"(c[1]), "+f"(c[2]), "+f"(c[3])
        : "r"(a[0]), "r"(a[1]), "r"(a[2]), "r"(a[3]), "r"(b[0]), "r"(b[1]));
}
__device__ __forceinline__ void cp16p(uint32_t dst, const void* src, bool valid) {
    int sz = valid ? 16 : 0;
    asm volatile("cp.async.cg.shared.global [%0], [%1], 16, %2;"
                 :: "r"(dst), "l"(src), "r"(sz) : "memory");
}

// smem layout per stage (fp16 elements): As[128*40] BsH[64*40] [BsL 64*40 if TWOTERM]
#define LDSW  40
#define ST_A  0
#define ST_BH (128 * LDSW)
#define ST_BL (128 * LDSW + 64 * LDSW)
#define STAGE2 (128 * LDSW + 2 * 64 * LDSW)   // two-term stage: 10240 elems
#define STAGE1 (128 * LDSW + 64 * LDSW)       // one-term stage:  7680 elems

// EPI: 0 = bias + fp16 out (emb h), 1 = fp16 out no bias (conv ht), 2 = bias + fp32 (out)
template<int KTOT, int EPI, bool TWOTERM>
__global__ __launch_bounds__(256)
void k_mma_gemm(const __half* __restrict__ A,
                const __half* __restrict__ Bhi, const __half* __restrict__ Blo,
                const float* __restrict__ bias,
                float* __restrict__ Cf, __half* __restrict__ Chf,
                int M, int Nout) {
    constexpr int BK = 32, NT = 4;
    constexpr int NCH = KTOT / BK;
    constexpr int STAGE = TWOTERM ? STAGE2 : STAGE1;
    extern __shared__ char smem_raw[];
    __half* smem = reinterpret_cast<__half*>(smem_raw);

    int tid = threadIdx.x;
    int lane = tid & 31, wid = tid >> 5;
    int wm = wid & 3, wn = wid >> 2;
    int g = lane >> 2, t2 = (lane & 3) * 2;

    int row0 = blockIdx.y * 128;
    int col0 = blockIdx.x * 64;

    float acc[2][NT][4];
    #pragma unroll
    for (int mt = 0; mt < 2; mt++)
        #pragma unroll
        for (int nt = 0; nt < NT; nt++)
            #pragma unroll
            for (int j = 0; j < 4; j++) acc[mt][nt][j] = 0.f;

    auto issue = [&](int c, int s) {
        int kc = c * BK;
        __half* base = smem + s * STAGE;
        #pragma unroll
        for (int u = tid; u < 512; u += 256) {
            int row = u >> 2, q = u & 3;
            int gr = row0 + row;
            bool ok = gr < M;
            const __half* pA = ok ? (A + (size_t)gr * KTOT + kc + q * 8) : A;
            cp16p((uint32_t)__cvta_generic_to_shared(base + ST_A + row * LDSW + q * 8), pA, ok);
        }
        {
            int u = tid;
            if (u < 256) {
                int row = u >> 2, q = u & 3;
                int gn = col0 + row;
                cp16p((uint32_t)__cvta_generic_to_shared(base + ST_BH + row * LDSW + q * 8),
                      Bhi + (size_t)gn * KTOT + kc + q * 8, true);
                if (TWOTERM)
                    cp16p((uint32_t)__cvta_generic_to_shared(base + ST_BL + row * LDSW + q * 8),
                          Blo + (size_t)gn * KTOT + kc + q * 8, true);
            }
        }
        asm volatile("cp.async.commit_group;" ::: "memory");
    };

    issue(0, 0);

    for (int c = 0; c < NCH; c++) {
        int s = c & 1;
        if (c + 1 < NCH) {
            issue(c + 1, (c + 1) & 1);
            asm volatile("cp.async.wait_group 1;" ::: "memory");
        } else {
            asm volatile("cp.async.wait_group 0;" ::: "memory");
        }
        __syncthreads();

        const __half* base = smem + s * STAGE;
        const __half* as  = base + ST_A;
        const __half* bsH = base + ST_BH;
        const __half* bsL = base + ST_BL;

        #pragma unroll
        for (int ko = 0; ko < BK; ko += 16) {
            uint32_t a[2][4];
            #pragma unroll
            for (int mt = 0; mt < 2; mt++) {
                int rb = wm * 32 + mt * 16;
                a[mt][0] = *reinterpret_cast<const uint32_t*>(as + (rb + g    ) * LDSW + ko + t2    );
                a[mt][1] = *reinterpret_cast<const uint32_t*>(as + (rb + g + 8) * LDSW + ko + t2    );
                a[mt][2] = *reinterpret_cast<const uint32_t*>(as + (rb + g    ) * LDSW + ko + t2 + 8);
                a[mt][3] = *reinterpret_cast<const uint32_t*>(as + (rb + g + 8) * LDSW + ko + t2 + 8);
            }
            uint32_t bh[NT][2], bl[NT][2];
            #pragma unroll
            for (int nt = 0; nt < NT; nt++) {
                int nb = wn * 32 + nt * 8 + g;
                bh[nt][0] = *reinterpret_cast<const uint32_t*>(bsH + nb * LDSW + ko + t2    );
                bh[nt][1] = *reinterpret_cast<const uint32_t*>(bsH + nb * LDSW + ko + t2 + 8);
                if (TWOTERM) {
                    bl[nt][0] = *reinterpret_cast<const uint32_t*>(bsL + nb * LDSW + ko + t2    );
                    bl[nt][1] = *reinterpret_cast<const uint32_t*>(bsL + nb * LDSW + ko + t2 + 8);
                }
            }
            #pragma unroll
            for (int mt = 0; mt < 2; mt++)
                #pragma unroll
                for (int nt = 0; nt < NT; nt++) {
                    mma16816(acc[mt][nt], a[mt], bh[nt]);
                    if (TWOTERM) mma16816(acc[mt][nt], a[mt], bl[nt]);
                }
        }
        __syncthreads();
    }

    #pragma unroll
    for (int mt = 0; mt < 2; mt++) {
        int rbase = row0 + wm * 32 + mt * 16;
        #pragma unroll
        for (int half = 0; half < 2; half++) {
            int r = rbase + g + half * 8;
            if (r >= M) continue;
            #pragma unroll
            for (int nt = 0; nt < NT; nt++) {
                int c = col0 + wn * 32 + nt * 8 + t2;
                float v0 = acc[mt][nt][half * 2 + 0];
                float v1 = acc[mt][nt][half * 2 + 1];
                if (EPI != 1) { v0 += bias[c]; v1 += bias[c + 1]; }
                if (EPI == 2) {
                    *reinterpret_cast<float2*>(&Cf[(size_t)r * Nout + c]) = make_float2(v0, v1);
                } else {
                    *reinterpret_cast<__half2*>(&Chf[(size_t)r * Nout + c]) =
                        __floats2half2_rn(v0, v1);
                }
            }
        }
    }
}

// ---------------- fused gather aggregation (fp16 in, fp16 out) ----------------
__device__ __forceinline__ void hfma8(float* acc, uint4 v, float w) {
    const __half2* h = reinterpret_cast<const __half2*>(&v);
    #pragma unroll
    for (int z = 0; z < 4; z++) {
        float2 f = __half22float2(h[z]);
        acc[z * 2]     += f.x * w;
        acc[z * 2 + 1] += f.y * w;
    }
}

__global__ __launch_bounds__(256)
void k_gather(const __half* __restrict__ ht, const int2* __restrict__ csr,
              const int* __restrict__ rowptr, const int* __restrict__ cnt,
              const float* __restrict__ b,
              __half* __restrict__ hout, int n) {
    int warp = (blockIdx.x * blockDim.x + threadIdx.x) >> 5;
    int lane = threadIdx.x & 31;
    if (warp >= n) return;
    int i = warp;

    float w0 = 1.0f / ((float)cnt[i] + 1.0f);   // dinv^2 exactly
    float acc[8] = {0.f, 0.f, 0.f, 0.f, 0.f, 0.f, 0.f, 0.f};

    // self term
    {
        uint4 v = reinterpret_cast<const uint4*>(ht + (size_t)i * DH)[lane];
        hfma8(acc, v, w0);
    }

    int beg = rowptr[i], end = rowptr[i + 1];
    int j = beg;
    for (; j + 1 < end; j += 2) {
        int2 e0 = csr[j], e1 = csr[j + 1];
        uint4 v0 = reinterpret_cast<const uint4*>(ht + (size_t)e0.x * DH)[lane];
        uint4 v1 = reinterpret_cast<const uint4*>(ht + (size_t)e1.x * DH)[lane];
        hfma8(acc, v0, __int_as_float(e0.y));
        hfma8(acc, v1, __int_as_float(e1.y));
    }
    if (j < end) {
        int2 e0 = csr[j];
        uint4 v0 = reinterpret_cast<const uint4*>(ht + (size_t)e0.x * DH)[lane];
        hfma8(acc, v0, __int_as_float(e0.y));
    }

    const float4* bp = reinterpret_cast<const float4*>(b);
    float4 b0 = bp[lane * 2], b1 = bp[lane * 2 + 1];
    float bb[8] = { b0.x, b0.y, b0.z, b0.w, b1.x, b1.y, b1.z, b1.w };

    __half hh[8];
    #pragma unroll
    for (int q = 0; q < 8; q++)
        hh[q] = __float2half_rn(tanhf(acc[q] + bb[q]));
    *reinterpret_cast<uint4*>(hout + (size_t)i * DH + lane * 8) = *reinterpret_cast<uint4*>(hh);
}

// ---------------- launcher ----------------
extern "C" void kernel_launch(void* const* d_in, const int* in_sizes, int n_in,
                              void* d_out, int out_size) {
    const float* x      = (const float*)d_in[0];
    const int*   eidx   = (const int*)  d_in[1];
    const float* W_emb  = (const float*)d_in[2];
    const float* b_emb  = (const float*)d_in[3];
    const float* W_conv = (const float*)d_in[4];
    const float* b_conv = (const float*)d_in[5];
    const float* W_out  = (const float*)d_in[6];
    const float* b_out  = (const float*)d_in[7];
    float* out = (float*)d_out;

    int E = in_sizes[1] / 2;
    if (E > E_MAX) E = E_MAX;
    const int* src = eidx;
    const int* dst = eidx + E;
    const int n = N_NODES;

    __half *xh, *h, *ht;
    int *cnt, *partial, *rowptr, *cursor;
    int2 *csr;
    __half *wembh, *wembl, *wconvh, *wouth, *woutl;
    cudaGetSymbolAddress((void**)&cnt,    g_cnt);
    cudaGetSymbolAddress((void**)&partial,g_partial);
    cudaGetSymbolAddress((void**)&rowptr, g_rowptr);
    cudaGetSymbolAddress((void**)&cursor, g_cursor);
    cudaGetSymbolAddress((void**)&csr,    g_csr);
    cudaGetSymbolAddress((void**)&xh,   g_x);
    cudaGetSymbolAddress((void**)&h,    g_h);
    cudaGetSymbolAddress((void**)&ht,   g_ht);
    cudaGetSymbolAddress((void**)&wembh, g_wembh);
    cudaGetSymbolAddress((void**)&wembl, g_wembl);
    cudaGetSymbolAddress((void**)&wconvh, g_wconvh);
    cudaGetSymbolAddress((void**)&wouth, g_wouth);
    cudaGetSymbolAddress((void**)&woutl, g_woutl);

    const int SMEM_G2 = 2 * STAGE2 * (int)sizeof(__half);   // 40960
    const int SMEM_G1 = 2 * STAGE1 * (int)sizeof(__half);   // 30720
    cudaFuncSetAttribute(k_mma_gemm<DIN, 0, true>,  cudaFuncAttributeMaxDynamicSharedMemorySize, SMEM_G2);
    cudaFuncSetAttribute(k_mma_gemm<DH, 1, false>,  cudaFuncAttributeMaxDynamicSharedMemorySize, SMEM_G1);
    cudaFuncSetAttribute(k_mma_gemm<DH, 2, true>,   cudaFuncAttributeMaxDynamicSharedMemorySize, SMEM_G2);

    // CSR build
    k_zero <<<(n + 255) / 256, 256>>>(cnt, n);
    k_count<<<(E + 255) / 256, 256>>>(dst, cnt, E);
    k_scan1<<<SCAN_NB, 256>>>(cnt, partial, n);
    k_scan2<<<1, 64>>>(partial, rowptr, SCAN_NB, n);
    k_scan3<<<SCAN_NB, 256>>>(cnt, partial, rowptr, cursor, n);
    k_fill <<<(E + 255) / 256, 256>>>(src, dst, cnt, cursor, csr, E);

    // conversions
    k_conv_x<<<(n * DIN + 255) / 256, 256>>>(x, xh, n * DIN);
    k_conv_w<<<(DIN * DH + 255) / 256, 256>>>(W_emb, wembh, wembl, DIN, DH);
    k_conv_wall<<<(LAYERS * DH * DH + 255) / 256, 256>>>(W_conv, wconvh);
    k_conv_w<<<(DH * DOUT + 255) / 256, 256>>>(W_out, wouth, woutl, DH, DOUT);

    int gy = (n + 127) / 128;

    // embedding: h = x @ W_emb + b_emb -> fp16 (2-term)
    {
        dim3 grid(DH / 64, gy);
        k_mma_gemm<DIN, 0, true><<<grid, 256, SMEM_G2>>>(xh, wembh, wembl, b_emb,
                                                         nullptr, h, n, DH);
    }

    int gather_blocks = (n * 32 + 255) / 256;
    for (int l = 0; l < LAYERS; l++) {
        const float* b = b_conv + (size_t)l * DH;
        dim3 grid(DH / 64, gy);
        k_mma_gemm<DH, 1, false><<<grid, 256, SMEM_G1>>>(h,
                                                         wconvh + (size_t)l * DH * DH,
                                                         nullptr,
                                                         nullptr, nullptr, ht, n, DH);
        k_gather<<<gather_blocks, 256>>>(ht, csr, rowptr, cnt, b, h, n);
    }

    // output: out = h @ W_out + b_out (2-term)
    {
        dim3 grid(DOUT / 64, gy);
        k_mma_gemm<DH, 2, true><<<grid, 256, SMEM_G2>>>(h, wouth, woutl, b_out,
                                                        out, nullptr, n, DOUT);
    }
}